// round 1
// baseline (speedup 1.0000x reference)
#include <cuda_runtime.h>
#include <math.h>

#define NN 50000
#define EE 800000
#define DD 96
#define HIDN 128
#define OUTD 8
#define BN_EPS 1e-5f
#define AGG_EPS 1e-6f

// ---------------- device scratch (no allocations allowed) ----------------
__device__ __align__(16) float g_h[NN * DD];
__device__ __align__(16) float g_A[NN * DD];
__device__ __align__(16) float g_B[NN * DD];
__device__ __align__(16) float g_D[NN * DD];
__device__ __align__(16) float g_E[NN * DD];
__device__ __align__(16) float g_num[NN * DD];
__device__ __align__(16) float g_den[NN * DD];
__device__ __align__(16) float g_hnew[NN * DD];
__device__ __align__(16) float g_e[EE * DD];
__device__ __align__(16) float g_enew[EE * DD];
__device__ __align__(16) float g_sums[4 * DD];   // esum, esumsq, hsum, hsumsq
__device__ __align__(16) float g_scale_e[DD], g_shift_e[DD];
__device__ __align__(16) float g_scale_h[DD], g_shift_h[DD];

// ---------------- input embeddings ----------------
__global__ void k_embed_h(const float* __restrict__ h1, const float* __restrict__ h2,
                          const float* __restrict__ z, const float* __restrict__ W,
                          const float* __restrict__ b) {
    int idx = blockIdx.x * blockDim.x + threadIdx.x;
    if (idx >= NN * DD) return;
    int row = idx / DD, col = idx % DD;
    float acc = b[col];
    const float* x1 = h1 + row * 6;
#pragma unroll
    for (int k = 0; k < 6; k++) acc += x1[k] * W[k * DD + col];
    const float* x2 = h2 + row * 4;
#pragma unroll
    for (int k = 0; k < 4; k++) acc += x2[k] * W[(6 + k) * DD + col];
    const float* x3 = z + row * 16;
#pragma unroll
    for (int k = 0; k < 16; k++) acc += x3[k] * W[(10 + k) * DD + col];
    g_h[idx] = acc;
}

__global__ void k_embed_e(const float* __restrict__ ef, const float* __restrict__ W,
                          const float* __restrict__ b) {
    long long idx = (long long)blockIdx.x * blockDim.x + threadIdx.x;
    if (idx >= (long long)EE * DD) return;
    int row = (int)(idx / DD), col = (int)(idx % DD);
    const float* x = ef + (long long)row * 4;
    float acc = b[col];
#pragma unroll
    for (int k = 0; k < 4; k++) acc += x[k] * W[k * DD + col];
    g_e[idx] = acc;
}

// ---------------- zero per-layer accumulators ----------------
__global__ void k_zero() {
    int idx = blockIdx.x * blockDim.x + threadIdx.x;
    const float4 z4 = make_float4(0.f, 0.f, 0.f, 0.f);
    if (idx < NN * DD / 4) {
        ((float4*)g_num)[idx] = z4;
        ((float4*)g_den)[idx] = z4;
    }
    if (idx < DD) {
        g_sums[idx] = 0.f; g_sums[DD + idx] = 0.f;
        g_sums[2 * DD + idx] = 0.f; g_sums[3 * DD + idx] = 0.f;
    }
}

// ---------------- node GEMM: out[M,96] = X[M,96] @ W[96,96] + b ----------------
__global__ __launch_bounds__(256) void k_gemm96(const float* __restrict__ X,
                                                const float* __restrict__ W,
                                                const float* __restrict__ bias,
                                                float* __restrict__ out, int M) {
    extern __shared__ float sm[];
    float* Ws = sm;            // 96*96
    float* Xs = sm + 96 * 96;  // 64*96
    int tid = threadIdx.x;
    int m0 = blockIdx.x * 64;

    for (int i = tid; i < 96 * 96 / 4; i += 256)
        ((float4*)Ws)[i] = ((const float4*)W)[i];
    for (int i = tid; i < 64 * 96 / 4; i += 256) {
        int gr = m0 + (i / 24);
        float4 v = make_float4(0.f, 0.f, 0.f, 0.f);
        if (gr < M) v = ((const float4*)X)[(long long)m0 * 24 + i];
        ((float4*)Xs)[i] = v;
    }
    __syncthreads();

    int tc = tid & 31, tw = tid >> 5;
    float acc[8][3];
#pragma unroll
    for (int r = 0; r < 8; r++) { acc[r][0] = 0.f; acc[r][1] = 0.f; acc[r][2] = 0.f; }

    const float* wp = Ws + tc;
    const float* xp = Xs + tw * 96;
#pragma unroll 8
    for (int k = 0; k < 96; k++) {
        float w0 = wp[0], w1 = wp[32], w2 = wp[64];
        wp += 96;
#pragma unroll
        for (int r = 0; r < 8; r++) {
            float xv = xp[768 * r + k];
            acc[r][0] += xv * w0; acc[r][1] += xv * w1; acc[r][2] += xv * w2;
        }
    }
    float b0 = bias[tc], b1 = bias[tc + 32], b2 = bias[tc + 64];
#pragma unroll
    for (int r = 0; r < 8; r++) {
        int row = m0 + tw + r * 8;
        if (row < M) {
            float* o = out + (long long)row * 96;
            o[tc] = acc[r][0] + b0;
            o[tc + 32] = acc[r][1] + b1;
            o[tc + 64] = acc[r][2] + b2;
        }
    }
}

// ---------------- fused edge layer ----------------
// Load stage (optional): e += relu(bn(e_new_prev)) using scale/shift from prev layer.
// GEMM: Ce = e @ WC.  Epilogue: e_new = Ce + bC + Dh[src] + Eh[dst];
// sig = sigmoid(e_new); atomic num/den; BN-e moment accumulation; store e_new.
__global__ __launch_bounds__(256) void k_gemm_edge(const float* __restrict__ WC,
                                                   const float* __restrict__ bC,
                                                   const int* __restrict__ src,
                                                   const int* __restrict__ dst,
                                                   int fuse) {
    extern __shared__ float sm[];
    float* Ws = sm;
    float* Xs = sm + 96 * 96;
    __shared__ float s_sum[96], s_sq[96];
    int tid = threadIdx.x;
    if (tid < 96) { s_sum[tid] = 0.f; s_sq[tid] = 0.f; }

    int e0 = blockIdx.x * 64;
    for (int i = tid; i < 96 * 96 / 4; i += 256)
        ((float4*)Ws)[i] = ((const float4*)WC)[i];
    for (int i = tid; i < 64 * 96 / 4; i += 256) {
        long long gi = (long long)e0 * 24 + i;
        float4 v = ((const float4*)g_e)[gi];
        if (fuse) {
            float4 en = ((const float4*)g_enew)[gi];
            int col = (i % 24) * 4;
            v.x += fmaxf(0.f, en.x * g_scale_e[col] + g_shift_e[col]);
            v.y += fmaxf(0.f, en.y * g_scale_e[col + 1] + g_shift_e[col + 1]);
            v.z += fmaxf(0.f, en.z * g_scale_e[col + 2] + g_shift_e[col + 2]);
            v.w += fmaxf(0.f, en.w * g_scale_e[col + 3] + g_shift_e[col + 3]);
            ((float4*)g_e)[gi] = v;
        }
        ((float4*)Xs)[i] = v;
    }
    __syncthreads();

    int tc = tid & 31, tw = tid >> 5;
    float acc[8][3];
#pragma unroll
    for (int r = 0; r < 8; r++) { acc[r][0] = 0.f; acc[r][1] = 0.f; acc[r][2] = 0.f; }

    const float* wp = Ws + tc;
    const float* xp = Xs + tw * 96;
#pragma unroll 8
    for (int k = 0; k < 96; k++) {
        float w0 = wp[0], w1 = wp[32], w2 = wp[64];
        wp += 96;
#pragma unroll
        for (int r = 0; r < 8; r++) {
            float xv = xp[768 * r + k];
            acc[r][0] += xv * w0; acc[r][1] += xv * w1; acc[r][2] += xv * w2;
        }
    }

    float b0 = bC[tc], b1 = bC[tc + 32], b2 = bC[tc + 64];
    float ssum0 = 0.f, ssum1 = 0.f, ssum2 = 0.f;
    float ssq0 = 0.f, ssq1 = 0.f, ssq2 = 0.f;
#pragma unroll
    for (int r = 0; r < 8; r++) {
        int row = e0 + tw + r * 8;
        int s = src[row], d = dst[row];
        const float* Dr = g_D + (long long)s * 96;
        const float* Er = g_E + (long long)d * 96;
        const float* Br = g_B + (long long)s * 96;
        float* nr = g_num + (long long)d * 96;
        float* dr = g_den + (long long)d * 96;
        float* er = g_enew + (long long)row * 96;

        float v0 = acc[r][0] + b0 + Dr[tc] + Er[tc];
        float v1 = acc[r][1] + b1 + Dr[tc + 32] + Er[tc + 32];
        float v2 = acc[r][2] + b2 + Dr[tc + 64] + Er[tc + 64];
        er[tc] = v0; er[tc + 32] = v1; er[tc + 64] = v2;
        ssum0 += v0; ssum1 += v1; ssum2 += v2;
        ssq0 += v0 * v0; ssq1 += v1 * v1; ssq2 += v2 * v2;
        float sg0 = 1.f / (1.f + __expf(-v0));
        float sg1 = 1.f / (1.f + __expf(-v1));
        float sg2 = 1.f / (1.f + __expf(-v2));
        atomicAdd(nr + tc,       sg0 * Br[tc]);
        atomicAdd(nr + tc + 32,  sg1 * Br[tc + 32]);
        atomicAdd(nr + tc + 64,  sg2 * Br[tc + 64]);
        atomicAdd(dr + tc,       sg0);
        atomicAdd(dr + tc + 32,  sg1);
        atomicAdd(dr + tc + 64,  sg2);
    }
    atomicAdd(&s_sum[tc], ssum0);       atomicAdd(&s_sq[tc], ssq0);
    atomicAdd(&s_sum[tc + 32], ssum1);  atomicAdd(&s_sq[tc + 32], ssq1);
    atomicAdd(&s_sum[tc + 64], ssum2);  atomicAdd(&s_sq[tc + 64], ssq2);
    __syncthreads();
    if (tid < 96) {
        atomicAdd(&g_sums[tid], s_sum[tid]);
        atomicAdd(&g_sums[DD + tid], s_sq[tid]);
    }
}

// ---------------- h_new = Ah + num/(den+eps), accumulate BN-h moments ----------------
__global__ __launch_bounds__(384) void k_hnew() {
    __shared__ float ssum[96], ssq[96];
    int tid = threadIdx.x;
    int col = tid % 96, yr = tid / 96;
    if (tid < 96) { ssum[tid] = 0.f; ssq[tid] = 0.f; }
    __syncthreads();
    float sm = 0.f, sq = 0.f;
    for (int row = blockIdx.x * 4 + yr; row < NN; row += gridDim.x * 4) {
        int i = row * 96 + col;
        float v = g_A[i] + g_num[i] / (g_den[i] + AGG_EPS);
        g_hnew[i] = v;
        sm += v; sq += v * v;
    }
    atomicAdd(&ssum[col], sm);
    atomicAdd(&ssq[col], sq);
    __syncthreads();
    if (tid < 96) {
        atomicAdd(&g_sums[2 * DD + tid], ssum[tid]);
        atomicAdd(&g_sums[3 * DD + tid], ssq[tid]);
    }
}

// ---------------- finalize BN stats -> scale/shift ----------------
__global__ void k_finalize(int which, const float* __restrict__ g,
                           const float* __restrict__ b, float invM) {
    int c = threadIdx.x;
    if (c >= 96) return;
    int base = which * 2 * DD;
    float mu = g_sums[base + c] * invM;
    float var = g_sums[base + DD + c] * invM - mu * mu;
    float rstd = rsqrtf(var + BN_EPS);
    float sc = g[c] * rstd;
    float sh = b[c] - mu * sc;
    if (which == 0) { g_scale_e[c] = sc; g_shift_e[c] = sh; }
    else            { g_scale_h[c] = sc; g_shift_h[c] = sh; }
}

// ---------------- h += relu(bn(h_new)) ----------------
__global__ void k_update_h() {
    int i4 = blockIdx.x * blockDim.x + threadIdx.x;
    if (i4 >= NN * DD / 4) return;
    int col = (i4 * 4) % 96;
    float4 hv = ((float4*)g_h)[i4];
    float4 nv = ((const float4*)g_hnew)[i4];
    hv.x += fmaxf(0.f, nv.x * g_scale_h[col] + g_shift_h[col]);
    hv.y += fmaxf(0.f, nv.y * g_scale_h[col + 1] + g_shift_h[col + 1]);
    hv.z += fmaxf(0.f, nv.z * g_scale_h[col + 2] + g_shift_h[col + 2]);
    hv.w += fmaxf(0.f, nv.w * g_scale_h[col + 3] + g_shift_h[col + 3]);
    ((float4*)g_h)[i4] = hv;
}

// ---------------- MLP head: out = max_action * tanh(relu(h@W1+b1)@W2+b2) ----------------
__global__ __launch_bounds__(128) void k_head(const float* __restrict__ W1,
                                              const float* __restrict__ b1,
                                              const float* __restrict__ W2,
                                              const float* __restrict__ b2,
                                              const float* __restrict__ maxa,
                                              float* __restrict__ out) {
    __shared__ float hs[8][96];
    __shared__ float hid[8][HIDN];
    int r0 = blockIdx.x * 8;
    int tid = threadIdx.x;
    for (int i = tid; i < 8 * 96; i += 128) {
        int r = i / 96, c = i % 96;
        int row = r0 + r;
        hs[r][c] = (row < NN) ? g_h[(long long)row * 96 + c] : 0.f;
    }
    __syncthreads();
    float acc[8];
#pragma unroll
    for (int r = 0; r < 8; r++) acc[r] = b1[tid];
#pragma unroll 4
    for (int k = 0; k < 96; k++) {
        float w = W1[k * HIDN + tid];
#pragma unroll
        for (int r = 0; r < 8; r++) acc[r] += hs[r][k] * w;
    }
#pragma unroll
    for (int r = 0; r < 8; r++) hid[r][tid] = fmaxf(acc[r], 0.f);
    __syncthreads();
    if (tid < 64) {
        int r = tid >> 3, c = tid & 7;
        int row = r0 + r;
        if (row < NN) {
            float a = b2[c];
#pragma unroll 8
            for (int k = 0; k < HIDN; k++) a += hid[r][k] * W2[k * OUTD + c];
            out[(long long)row * OUTD + c] = maxa[row] * tanhf(a);
        }
    }
}

// ---------------- launch ----------------
extern "C" void kernel_launch(void* const* d_in, const int* in_sizes, int n_in,
                              void* d_out, int out_size) {
    const float* h1 = (const float*)d_in[0];
    const float* h2 = (const float*)d_in[1];
    const float* z = (const float*)d_in[2];
    const float* efeat = (const float*)d_in[3];
    const float* max_action = (const float*)d_in[4];
    const float* Wh_emb = (const float*)d_in[5];
    const float* bh_emb = (const float*)d_in[6];
    const float* We_emb = (const float*)d_in[7];
    const float* be_emb = (const float*)d_in[8];
    const float* WA = (const float*)d_in[9];
    const float* bA = (const float*)d_in[10];
    const float* WB = (const float*)d_in[11];
    const float* bB = (const float*)d_in[12];
    const float* WC = (const float*)d_in[13];
    const float* bC = (const float*)d_in[14];
    const float* WD = (const float*)d_in[15];
    const float* bD = (const float*)d_in[16];
    const float* WE = (const float*)d_in[17];
    const float* bE = (const float*)d_in[18];
    const float* bn_h_g = (const float*)d_in[19];
    const float* bn_h_b = (const float*)d_in[20];
    const float* bn_e_g = (const float*)d_in[21];
    const float* bn_e_b = (const float*)d_in[22];
    const float* W1 = (const float*)d_in[23];
    const float* b1 = (const float*)d_in[24];
    const float* W2 = (const float*)d_in[25];
    const float* b2 = (const float*)d_in[26];
    const int* src = (const int*)d_in[27];
    const int* dst = (const int*)d_in[28];
    float* out = (float*)d_out;

    float *p_h, *p_A, *p_B, *p_D, *p_E;
    cudaGetSymbolAddress((void**)&p_h, g_h);
    cudaGetSymbolAddress((void**)&p_A, g_A);
    cudaGetSymbolAddress((void**)&p_B, g_B);
    cudaGetSymbolAddress((void**)&p_D, g_D);
    cudaGetSymbolAddress((void**)&p_E, g_E);

    const int smem_gemm = (96 * 96 + 64 * 96) * 4;  // 61440 B
    cudaFuncSetAttribute(k_gemm96, cudaFuncAttributeMaxDynamicSharedMemorySize, smem_gemm);
    cudaFuncSetAttribute(k_gemm_edge, cudaFuncAttributeMaxDynamicSharedMemorySize, smem_gemm);

    k_embed_h<<<(NN * DD + 255) / 256, 256>>>(h1, h2, z, Wh_emb, bh_emb);
    k_embed_e<<<(int)(((long long)EE * DD + 255) / 256), 256>>>(efeat, We_emb, be_emb);

    const int nblk = (NN + 63) / 64;   // 782
    const int eblk = EE / 64;          // 12500

    for (int l = 0; l < 4; l++) {
        const float* WAl = WA + l * DD * DD;
        const float* WBl = WB + l * DD * DD;
        const float* WCl = WC + l * DD * DD;
        const float* WDl = WD + l * DD * DD;
        const float* WEl = WE + l * DD * DD;

        k_gemm96<<<nblk, 256, smem_gemm>>>(p_h, WAl, bA + l * DD, p_A, NN);
        k_gemm96<<<nblk, 256, smem_gemm>>>(p_h, WBl, bB + l * DD, p_B, NN);
        k_gemm96<<<nblk, 256, smem_gemm>>>(p_h, WDl, bD + l * DD, p_D, NN);
        k_gemm96<<<nblk, 256, smem_gemm>>>(p_h, WEl, bE + l * DD, p_E, NN);

        k_zero<<<(NN * DD / 4 + 255) / 256, 256>>>();

        k_gemm_edge<<<eblk, 256, smem_gemm>>>(WCl, bC + l * DD, src, dst, l > 0 ? 1 : 0);

        if (l < 3)
            k_finalize<<<1, 96>>>(0, bn_e_g + l * DD, bn_e_b + l * DD, 1.f / EE);

        k_hnew<<<256, 384>>>();
        k_finalize<<<1, 96>>>(1, bn_h_g + l * DD, bn_h_b + l * DD, 1.f / NN);
        k_update_h<<<(NN * DD / 4 + 255) / 256, 256>>>();
    }

    k_head<<<NN / 8, 128>>>(W1, b1, W2, b2, max_action, out);
}